// round 17
// baseline (speedup 1.0000x reference)
#include <cuda_runtime.h>

// MBTR + analytic divergence, GB300 (sm_103a). Round 13 = R12 main loop
// (proven local optimum) with the per-block prologue hoisted into a
// precompute kernel:
//   - sort + pair-table (2304 entries/b) computed ONCE per b into __device__
//     global tables (1.8MB, L2-resident) instead of 768x (serial thread-0
//     sort + rsqrt/exp chains were on every block's critical path; band
//     sweep proved inner loop is NOT the binding constraint)
//   - precompute kernel also zeroes mbtr (absorbs old zero kernel)
//   - main kernel prologue: coalesced 9KB table load from L2 + 1 sync

#define NB   32
#define NA   48
#define NE   4
#define NG   128
#define ATH  8                  // atoms per block
#define GC   32                 // grid points per block
#define NTHR (ATH * GC)         // 256
#define NTHIRD (NA / ATH)       // 6
#define NGCH   (NG / GC)        // 4
#define NBLK (NB * NGCH * NTHIRD)   // 768
#define MBTR_SZ (NB * NE * NE * NG) // 65536
#define ROWQ (ATH * 3)          // 24 floats per (slot,g) row owned by block
#define ACCPAD (ROWQ + 1)       // 25

__device__ float4 g_tabA[NB][NA][NA];   // {gfs, wf*C, gsq, -ux}
__device__ float2 g_tabB[NB][NA][NA];   // {-uy, -uz}
__device__ int    g_segs[NE + 1];

static __device__ __forceinline__ float ex2f(float x) {
    float y;
    asm("ex2.approx.ftz.f32 %0, %1;" : "=f"(y) : "f"(x));
    return y;
}

// One block per b (512 threads): sort by species, fill pair tables, zero mbtr.
__global__ void __launch_bounds__(512)
precompute_kernel(const float* __restrict__ r,
                  const int*   __restrict__ z,
                  const float* __restrict__ grid,
                  float*       __restrict__ out)
{
    const int b = blockIdx.x;
    const int t = threadIdx.x;

    __shared__ float4 rs[NA];
    __shared__ int    zs[NA], S[NA];

    const float INV_SIGMA = 20.0f;

    if (t < NA) {
        zs[t] = z[t];
        const float* rp = r + (b * NA + t) * 3;
        rs[t] = make_float4(rp[0], rp[1], rp[2], 0.f);
    }
    // zero mbtr slice for this b (2048 floats)
    for (int i = t; i < NE * NE * NG; i += 512)
        out[b * (NE * NE * NG) + i] = 0.f;
    __syncthreads();

    if (t == 0) {
        int cnt[NE] = {0, 0, 0, 0};
        for (int j = 0; j < NA; j++) cnt[zs[j]]++;
        int off = 0, pos[NE];
        int sg[NE + 1];
        sg[0] = 0;
        #pragma unroll
        for (int e = 0; e < NE; e++) { pos[e] = off; off += cnt[e]; sg[e + 1] = off; }
        for (int j = 0; j < NA; j++) S[pos[zs[j]]++] = j;
        if (b == 0) {
            #pragma unroll
            for (int e = 0; e <= NE; e++) g_segs[e] = sg[e];
        }
    }
    __syncthreads();

    const float gdx = grid[1] - grid[0];
    const float C   = gdx * 0.3989422804014327f * INV_SIGMA;
    for (int f = t; f < NA * NA; f += 512) {
        const int jp = f / NA;
        const int a2 = f - jp * NA;
        const int p  = S[jp];
        if (p == a2) {
            g_tabA[b][jp][a2] = make_float4(0.f, 0.f, 0.f, 0.f);
            g_tabB[b][jp][a2] = make_float2(0.f, 0.f);
        } else {
            const float4 ra = rs[a2], rp = rs[p];
            const float dx = ra.x - rp.x, dy = ra.y - rp.y, dz = ra.z - rp.z;
            const float d2   = fmaf(dx, dx, fmaf(dy, dy, dz * dz));
            const float invd = rsqrtf(d2);
            const float d    = d2 * invd;
            const float wf   = __expf(-d);
            const float gfs  = invd * INV_SIGMA;
            g_tabA[b][jp][a2] = make_float4(gfs, wf * C,
                                            invd * invd * INV_SIGMA, -dx * invd);
            g_tabB[b][jp][a2] = make_float2(-dy * invd, -dz * invd);
        }
    }
}

__global__ void __launch_bounds__(NTHR, 4)
mbtr_kernel(const float* __restrict__ r,
            const int*   __restrict__ z,
            const float* __restrict__ grid,
            float*       __restrict__ out)
{
    const int bid    = blockIdx.x;
    const int third  = bid % NTHIRD;
    const int tmp    = bid / NTHIRD;
    const int gchunk = tmp % NGCH;
    const int b      = tmp / NGCH;

    const int t    = threadIdx.x;
    const int al   = t >> 5;            // warp id = local atom
    const int lane = t & 31;
    const int a    = third * ATH + al;  // global atom
    const int g    = gchunk * GC + lane;

    __shared__ float4 tabA[NA][ATH];    // {gfs, wf*C, gsq, -ux}
    __shared__ float2 tabB[NA][ATH];    // {-uy, -uz}
    __shared__ float  gfsT[ATH][NA];    // gfs, lane-major readable
    __shared__ float  acc[NE][GC][ACCPAD];
    __shared__ int    zs[NA], segs[NE + 1];

    const float CM   = -0.72134752044448170f;   // -0.5 * log2(e)
    const float BAND = 5.0f;                    // sigma units

    if (t < NA) zs[t] = z[t];
    if (t >= 64 && t < 64 + NE + 1) segs[t - 64] = g_segs[t - 64];

    // Coalesced table load from L2: 384 entries, 8 per row contiguous.
    #pragma unroll
    for (int it = 0; it < (NA * ATH + NTHR - 1) / NTHR; it++) {
        const int f = it * NTHR + t;
        if (f < NA * ATH) {
            const int jp  = f >> 3;
            const int al2 = f & (ATH - 1);
            const float4 A = g_tabA[b][jp][third * ATH + al2];
            tabA[jp][al2] = A;
            tabB[jp][al2] = g_tabB[b][jp][third * ATH + al2];
            gfsT[al2][jp] = A.x;
        }
    }
    __syncthreads();

    const int   za = zs[a];
    const float gg = grid[g] * 20.0f;   // grid/sigma
    const float bandlo = __shfl_sync(0xffffffffu, gg, 0)  - BAND;
    const float bandhi = __shfl_sync(0xffffffffu, gg, 31) + BAND;

    // 48-bit active-pair mask (warp-uniform).
    const float f0 = gfsT[al][lane];
    const unsigned m0 = __ballot_sync(0xffffffffu, f0 > bandlo && f0 < bandhi);
    const float f1 = (lane < 16) ? gfsT[al][32 + lane] : 0.f;
    const unsigned m1 = __ballot_sync(0xffffffffu,
                                      lane < 16 && f1 > bandlo && f1 < bandhi);
    const unsigned long long mask =
        (unsigned long long)m0 | ((unsigned long long)(m1 & 0xFFFFu) << 32);

    float* const mb = out + (((b * NE + za) * NE) * NG) + g;

    #pragma unroll
    for (int e = 0; e < NE; e++) {
        unsigned long long m =
            mask & ((1ull << segs[e + 1]) - (1ull << segs[e]));
        float wv = 0.f, xv = 0.f, yv = 0.f, zv = 0.f;
        while (m) {
            const int jp = __ffsll((long long)m) - 1;
            m &= m - 1;
            const float4 A  = tabA[jp][al];     // broadcast LDS
            const float2 Bv = tabB[jp][al];
            const float tt = gg - A.x;
            const float E  = ex2f((CM * tt) * tt);
            const float wg = A.y * E;
            const float s  = fmaf(wg * A.z, tt, wg);
            wv += wg;
            xv = fmaf(s, A.w,  xv);
            yv = fmaf(s, Bv.x, yv);
            zv = fmaf(s, Bv.y, zv);
        }
        // mbtr: coalesced RED.ADD per warp per segment.
        atomicAdd(mb + e * NG, wv);
        acc[e][lane][al * 3 + 0] = xv;
        acc[e][lane][al * 3 + 1] = yv;
        acc[e][lane][al * 3 + 2] = zv;
    }
    __syncthreads();

    // Transposed div store: 16 slots x 32 g x 24 floats; thread owns 3 cells.
    int gq[3], qq[3], zaq[3];
    #pragma unroll
    for (int k = 0; k < 3; k++) {
        const int f = k * NTHR + t;
        gq[k]  = f / ROWQ;
        qq[k]  = f - gq[k] * ROWQ;
        zaq[k] = zs[third * ATH + qq[k] / 3];
    }
    float* __restrict__ dbase = out + MBTR_SZ
        + ((size_t)(b * NE * NE) * NG + gchunk * GC) * (NA * 3)
        + third * ROWQ;

    #pragma unroll
    for (int slot = 0; slot < NE * NE; slot++) {
        const int e1 = slot >> 2, e2 = slot & 3;
        #pragma unroll
        for (int k = 0; k < 3; k++) {
            float v = 0.f;
            if (zaq[k] == e1) v += acc[e2][gq[k]][qq[k]];
            if (zaq[k] == e2) v += acc[e1][gq[k]][qq[k]];
            dbase[(size_t)slot * (NG * NA * 3) + gq[k] * (NA * 3) + qq[k]] = v;
        }
    }
}

extern "C" void kernel_launch(void* const* d_in, const int* in_sizes, int n_in,
                              void* d_out, int out_size)
{
    const float* r    = (const float*)d_in[0];
    const int*   z    = (const int*)  d_in[1];
    const float* grid = (const float*)d_in[2];
    float*       out  = (float*)d_out;

    precompute_kernel<<<NB, 512>>>(r, z, grid, out);
    mbtr_kernel<<<NBLK, NTHR>>>(r, z, grid, out);
}